// round 2
// baseline (speedup 1.0000x reference)
#include <cuda_runtime.h>
#include <math_constants.h>

#define NN 100000
#define FI 256
#define FH 128
#define FO 40

// ---------------- scratch (static device globals; no runtime allocation) ----
__device__ __align__(256) float g_deg[NN];
__device__ __align__(256) float g_dinv[NN];
__device__ __align__(256) float g_h1[NN * FH];    // x @ W1
__device__ __align__(256) float g_agg1[NN * FH];  // aggregated + relu (in place)
__device__ __align__(256) float g_h2[NN * FO];    // relu @ W2
__device__ __align__(256) float g_agg2[NN * FO];  // aggregated layer 2
__device__ int g_is64;                            // edge_index dtype flag

// ---------------- helpers ---------------------------------------------------
__device__ __forceinline__ void red_add_v4(float* p, float a, float b, float c, float d) {
    asm volatile("red.global.add.v4.f32 [%0], {%1,%2,%3,%4};"
                 :: "l"(p), "f"(a), "f"(b), "f"(c), "f"(d) : "memory");
}

// Read edge endpoint i (0..2E-1 linear over [src | dst]) honoring runtime dtype.
__device__ __forceinline__ int eidx(const void* p, long long i, int is64) {
    if (is64) return (int)((const long long*)p)[i];
    return ((const int*)p)[i];
}

// ---------------- dtype probe (int64 vs int32 edge_index) -------------------
__global__ void k_detect(const void* ei) {
    if (blockIdx.x == 0 && threadIdx.x == 0) {
        const long long* p = (const long long*)ei;
        int ok = 1;
        #pragma unroll
        for (int i = 0; i < 32; i++) {
            long long v = p[i];  // 256B read: in-bounds for both dtypes
            if (v < 0 || v >= NN) ok = 0;
        }
        g_is64 = ok;  // int32 data ~never passes (needs 32 zero hi-words)
    }
}

// ---------------- degree / normalization ------------------------------------
__global__ void k_deg_init() {
    int i = blockIdx.x * blockDim.x + threadIdx.x;
    if (i < NN) g_deg[i] = 1.0f;  // self loop
}

__global__ void k_deg_count(const void* ei, int E) {
    int i = blockIdx.x * blockDim.x + threadIdx.x;
    if (i < E) {
        int is64 = g_is64;
        int d = eidx(ei, (long long)E + i, is64);
        atomicAdd(&g_deg[d], 1.0f);
    }
}

__global__ void k_dinv() {
    int i = blockIdx.x * blockDim.x + threadIdx.x;
    if (i < NN) g_dinv[i] = rsqrtf(fmaxf(g_deg[i], 1.0f));
}

// ---------------- GEMM1: h1 = x @ W1   (100000x256 @ 256x128) ---------------
// 128 threads = 128 output cols; 16 rows per block; K tiled by 64 in smem.
__global__ void k_gemm1(const float* __restrict__ x, const float* __restrict__ W) {
    __shared__ float Ws[64 * 128];  // 32 KB
    __shared__ float Xs[16 * 64];   // 4 KB
    int t = threadIdx.x;
    int row0 = blockIdx.x * 16;

    float acc[16];
    #pragma unroll
    for (int r = 0; r < 16; r++) acc[r] = 0.f;

    for (int kt = 0; kt < 4; kt++) {
        for (int i = 0; i < 64; i++)
            Ws[i * 128 + t] = W[(kt * 64 + i) * 128 + t];
        #pragma unroll
        for (int s = 0; s < 8; s++) {
            int idx = t + 128 * s;
            int r = idx >> 6, c = idx & 63;
            int gr = row0 + r;
            Xs[idx] = (gr < NN) ? x[(long long)gr * FI + kt * 64 + c] : 0.f;
        }
        __syncthreads();

        const float4* X4 = (const float4*)Xs;
        #pragma unroll
        for (int k = 0; k < 64; k += 4) {
            float w0 = Ws[k * 128 + t];
            float w1 = Ws[(k + 1) * 128 + t];
            float w2 = Ws[(k + 2) * 128 + t];
            float w3 = Ws[(k + 3) * 128 + t];
            #pragma unroll
            for (int r = 0; r < 16; r++) {
                float4 xv = X4[r * 16 + (k >> 2)];
                acc[r] = fmaf(xv.x, w0, acc[r]);
                acc[r] = fmaf(xv.y, w1, acc[r]);
                acc[r] = fmaf(xv.z, w2, acc[r]);
                acc[r] = fmaf(xv.w, w3, acc[r]);
            }
        }
        __syncthreads();
    }
    #pragma unroll
    for (int r = 0; r < 16; r++) {
        int gr = row0 + r;
        if (gr < NN) g_h1[(long long)gr * FH + t] = acc[r];
    }
}

// ---------------- layer-1 aggregate ------------------------------------------
__global__ void k_init1(const float* __restrict__ b1) {
    int i = blockIdx.x * blockDim.x + threadIdx.x;
    if (i < NN * FH) {
        int n = i >> 7, c = i & 127;
        float di = g_dinv[n];
        g_agg1[i] = b1[c] + g_h1[i] * di * di;  // self-loop contribution
    }
}

// one warp per edge, 32 lanes x float4 = 128 floats
__global__ void k_scat1(const void* __restrict__ ei, int E) {
    int w = (blockIdx.x * blockDim.x + threadIdx.x) >> 5;
    int lane = threadIdx.x & 31;
    if (w < E) {
        int is64 = g_is64;
        int s = eidx(ei, w, is64);
        int d = eidx(ei, (long long)E + w, is64);
        float nm = g_dinv[s] * g_dinv[d];
        const float4* hp = (const float4*)(g_h1 + (long long)s * FH);
        float4 v = hp[lane];
        red_add_v4(g_agg1 + (long long)d * FH + lane * 4,
                   v.x * nm, v.y * nm, v.z * nm, v.w * nm);
    }
}

__global__ void k_relu() {
    int i = blockIdx.x * blockDim.x + threadIdx.x;
    if (i < NN * FH) g_agg1[i] = fmaxf(g_agg1[i], 0.f);
}

// ---------------- GEMM2: h2 = relu(agg1) @ W2  (100000x128 @ 128x40) --------
// 160 threads = 40 cols x 4 row-groups; 16 rows per block; acc[4] per thread.
__global__ void k_gemm2(const float* __restrict__ W2) {
    __shared__ float Ws[128 * 40];  // 20 KB
    __shared__ float Xs[16 * 128];  // 8 KB
    int t = threadIdx.x;            // 0..159
    int tx = t % 40;
    int tg = t / 40;                // 0..3
    int row0 = blockIdx.x * 16;

    for (int s = t; s < 128 * 40; s += 160) Ws[s] = W2[s];
    for (int s = t; s < 16 * 128; s += 160) {
        int r = s >> 7, c = s & 127;
        int gr = row0 + r;
        Xs[s] = (gr < NN) ? g_agg1[(long long)gr * FH + c] : 0.f;
    }
    __syncthreads();

    float acc[4] = {0.f, 0.f, 0.f, 0.f};
    const float4* X4 = (const float4*)Xs;
    #pragma unroll
    for (int k = 0; k < 128; k += 4) {
        float w0 = Ws[k * 40 + tx];
        float w1 = Ws[(k + 1) * 40 + tx];
        float w2 = Ws[(k + 2) * 40 + tx];
        float w3 = Ws[(k + 3) * 40 + tx];
        #pragma unroll
        for (int r = 0; r < 4; r++) {
            float4 xv = X4[(tg * 4 + r) * 32 + (k >> 2)];
            acc[r] = fmaf(xv.x, w0, acc[r]);
            acc[r] = fmaf(xv.y, w1, acc[r]);
            acc[r] = fmaf(xv.z, w2, acc[r]);
            acc[r] = fmaf(xv.w, w3, acc[r]);
        }
    }
    #pragma unroll
    for (int r = 0; r < 4; r++) {
        int gr = row0 + tg * 4 + r;
        if (gr < NN) g_h2[(long long)gr * FO + tx] = acc[r];
    }
}

// ---------------- layer-2 aggregate ------------------------------------------
__global__ void k_init2(const float* __restrict__ b2) {
    int i = blockIdx.x * blockDim.x + threadIdx.x;
    if (i < NN * FO) {
        int n = i / 40, c = i - n * 40;
        float di = g_dinv[n];
        g_agg2[i] = b2[c] + g_h2[i] * di * di;
    }
}

// thread per (edge, float4-chunk): 10 chunks cover 40 floats
__global__ void k_scat2(const void* __restrict__ ei, int E) {
    long long idx = (long long)blockIdx.x * blockDim.x + threadIdx.x;
    if (idx < (long long)E * 10) {
        int e = (int)(idx / 10);
        int q = (int)(idx - (long long)e * 10);
        int is64 = g_is64;
        int s = eidx(ei, e, is64);
        int d = eidx(ei, (long long)E + e, is64);
        float nm = g_dinv[s] * g_dinv[d];
        const float4* hp = (const float4*)(g_h2 + (long long)s * FO);
        float4 v = hp[q];
        red_add_v4(g_agg2 + (long long)d * FO + q * 4,
                   v.x * nm, v.y * nm, v.z * nm, v.w * nm);
    }
}

// ---------------- log_softmax over 40 classes, one warp per row --------------
__global__ void k_lsm(float* __restrict__ out) {
    int row = (blockIdx.x * blockDim.x + threadIdx.x) >> 5;
    int lane = threadIdx.x & 31;
    if (row < NN) {
        const float* in = g_agg2 + (long long)row * FO;
        float v0 = in[lane];
        float v1 = (lane < 8) ? in[32 + lane] : -CUDART_INF_F;
        float m = fmaxf(v0, v1);
        #pragma unroll
        for (int o = 16; o; o >>= 1) m = fmaxf(m, __shfl_xor_sync(0xffffffffu, m, o));
        float s = expf(v0 - m) + ((lane < 8) ? expf(v1 - m) : 0.f);
        #pragma unroll
        for (int o = 16; o; o >>= 1) s += __shfl_xor_sync(0xffffffffu, s, o);
        float ls = m + logf(s);
        out[(long long)row * FO + lane] = v0 - ls;
        if (lane < 8) out[(long long)row * FO + 32 + lane] = v1 - ls;
    }
}

// ---------------- launch ------------------------------------------------------
extern "C" void kernel_launch(void* const* d_in, const int* in_sizes, int n_in,
                              void* d_out, int out_size) {
    const float* x  = (const float*)d_in[0];
    const void*  ei = d_in[1];                 // int64 or int32, probed on device
    const float* W1 = (const float*)d_in[2];
    const float* b1 = (const float*)d_in[3];
    const float* W2 = (const float*)d_in[4];
    const float* b2 = (const float*)d_in[5];
    float* out = (float*)d_out;
    int E = in_sizes[1] / 2;

    k_detect<<<1, 32>>>(ei);
    k_deg_init<<<(NN + 255) / 256, 256>>>();
    k_deg_count<<<(E + 255) / 256, 256>>>(ei, E);
    k_dinv<<<(NN + 255) / 256, 256>>>();

    k_gemm1<<<(NN + 15) / 16, 128>>>(x, W1);
    k_init1<<<(NN * FH + 255) / 256, 256>>>(b1);
    k_scat1<<<(E + 7) / 8, 256>>>(ei, E);       // 8 warps/block, warp per edge
    k_relu<<<(NN * FH + 255) / 256, 256>>>();

    k_gemm2<<<(NN + 15) / 16, 160>>>(W2);
    k_init2<<<(NN * FO + 255) / 256, 256>>>(b2);
    long long tot2 = (long long)E * 10;
    k_scat2<<<(unsigned)((tot2 + 255) / 256), 256>>>(ei, E);

    k_lsm<<<(NN + 7) / 8, 256>>>(out);
}